// round 1
// baseline (speedup 1.0000x reference)
#include <cuda_runtime.h>
#include <math.h>
#include <stdint.h>

// Problem constants
#define SDIM 2048
#define EDIM 2048
#define NH   16
#define NKV  4
#define DH   128
#define NHG  12
#define RDIM 32
#define NSYM 4
#define RLD  (NHG*RDIM)   // 384
#define KVLD (NKV*DH)     // 512

// Scratch (device globals: allocation-free rule)
static __device__ float g_q [SDIM*EDIM];
static __device__ float g_k [SDIM*KVLD];
static __device__ float g_v [SDIM*KVLD];
static __device__ float g_rq[SDIM*RLD];
static __device__ float g_rk[SDIM*RLD];
static __device__ float g_sc[(size_t)NH*SDIM*SDIM];   // scores / attn (256 MB)
static __device__ float g_ao[SDIM*EDIM];

// ---------------------------------------------------------------------------
// Generic NT GEMM: C[M,N] = A[M,K] @ B[N,K]^T. 128x128 tile, 256 thr, 8x8 micro.
// Requires M,N multiples of 128; K multiple of 8; all ld multiples of 4.
// ---------------------------------------------------------------------------
__global__ __launch_bounds__(256) void gemm_nt(
    const float* __restrict__ A, int lda,
    const float* __restrict__ B, int ldb,
    float* __restrict__ C, int ldc, int K)
{
    __shared__ float As[8][128];
    __shared__ float Bs[8][128];
    const int tid = threadIdx.x;
    const int ty = tid >> 4, tx = tid & 15;
    const int m0 = blockIdx.y << 7, n0 = blockIdx.x << 7;
    const int lrow = tid >> 1;
    const int lc4  = (tid & 1) << 2;
    const float* Ap = A + (size_t)(m0 + lrow) * lda + lc4;
    const float* Bp = B + (size_t)(n0 + lrow) * ldb + lc4;

    float acc[8][8];
#pragma unroll
    for (int i = 0; i < 8; i++)
#pragma unroll
        for (int j = 0; j < 8; j++) acc[i][j] = 0.f;

    for (int k0 = 0; k0 < K; k0 += 8) {
        float4 av = *(const float4*)(Ap + k0);
        float4 bv = *(const float4*)(Bp + k0);
        As[lc4+0][lrow] = av.x; As[lc4+1][lrow] = av.y;
        As[lc4+2][lrow] = av.z; As[lc4+3][lrow] = av.w;
        Bs[lc4+0][lrow] = bv.x; Bs[lc4+1][lrow] = bv.y;
        Bs[lc4+2][lrow] = bv.z; Bs[lc4+3][lrow] = bv.w;
        __syncthreads();
#pragma unroll
        for (int kk = 0; kk < 8; kk++) {
            float4 a0 = *(const float4*)&As[kk][ty*8];
            float4 a1 = *(const float4*)&As[kk][ty*8+4];
            float4 b0 = *(const float4*)&Bs[kk][tx*8];
            float4 b1 = *(const float4*)&Bs[kk][tx*8+4];
            float a[8] = {a0.x,a0.y,a0.z,a0.w,a1.x,a1.y,a1.z,a1.w};
            float b[8] = {b0.x,b0.y,b0.z,b0.w,b1.x,b1.y,b1.z,b1.w};
#pragma unroll
            for (int i = 0; i < 8; i++)
#pragma unroll
                for (int j = 0; j < 8; j++)
                    acc[i][j] = fmaf(a[i], b[j], acc[i][j]);
        }
        __syncthreads();
    }
#pragma unroll
    for (int i = 0; i < 8; i++) {
        float* Cp = C + (size_t)(m0 + ty*8 + i) * ldc + n0 + tx*8;
        *(float4*)(Cp)   = make_float4(acc[i][0],acc[i][1],acc[i][2],acc[i][3]);
        *(float4*)(Cp+4) = make_float4(acc[i][4],acc[i][5],acc[i][6],acc[i][7]);
    }
}

// ---------------------------------------------------------------------------
// Fused RMSNorm + RoPE over one (s, head). 128 threads, one per dim.
// ---------------------------------------------------------------------------
__global__ __launch_bounds__(128) void norm_rope(
    float* __restrict__ buf, const float* __restrict__ w, int ld)
{
    const int s = blockIdx.x, h = blockIdx.y, d = threadIdx.x;
    float* p = buf + (size_t)s * ld + h * DH;
    float v = p[d];
    float ss = v * v;
#pragma unroll
    for (int o = 16; o; o >>= 1) ss += __shfl_xor_sync(0xffffffffu, ss, o);
    __shared__ float r4[4];
    __shared__ float sh[DH];
    if ((d & 31) == 0) r4[d >> 5] = ss;
    __syncthreads();
    float tot = r4[0] + r4[1] + r4[2] + r4[3];
    float nv = v * rsqrtf(tot * (1.f / DH) + 1e-6f) * w[d];
    sh[d] = nv;
    __syncthreads();
    const int dm = d & 63;
    float e = (float)(2 * dm) * (1.f / DH);
    float f = 1.f / powf(10000.f, e);
    float ang = (float)s * f;
    float cs, sn;
    sincosf(ang, &sn, &cs);
    float rot = (d < 64) ? -sh[d + 64] : sh[d - 64];
    p[d] = nv * cs + rot * sn;
}

// ---------------------------------------------------------------------------
// Scores: for each head, lower-triangular 128x128 tiles of
//   scores = (q·k^T)*scale + bias, causal-masked entries written as 0
//   bias (h<12): gs * Rq_i·Rk_j   (h<4: gs*0.5*(Rq_i·Rk_j + Rq_j·Rk_i))
// ---------------------------------------------------------------------------
__global__ __launch_bounds__(256) void scores_kernel(const float* __restrict__ gscale)
{
    __shared__ float As[8][128];
    __shared__ float Bs[8][128];
    __shared__ float Rq_s[128][33];
    __shared__ float Rk_s[128][33];

    const int h = blockIdx.y;
    const int idx = blockIdx.x;
    int ti = (int)((sqrtf(8.f * idx + 1.f) - 1.f) * 0.5f);
    while ((ti + 1) * (ti + 2) / 2 <= idx) ti++;
    while (ti * (ti + 1) / 2 > idx) ti--;
    const int tj = idx - ti * (ti + 1) / 2;
    const int i0 = ti << 7, j0 = tj << 7;

    const int tid = threadIdx.x;
    const int ty = tid >> 4, tx = tid & 15;
    const int lrow = tid >> 1, lc4 = (tid & 1) << 2;
    const int kvh = h >> 2;

    const float* Ap = g_q + (size_t)(i0 + lrow) * EDIM + h * DH + lc4;
    const float* Bp = g_k + (size_t)(j0 + lrow) * KVLD + kvh * DH + lc4;

    float acc[8][8];
#pragma unroll
    for (int i = 0; i < 8; i++)
#pragma unroll
        for (int j = 0; j < 8; j++) acc[i][j] = 0.f;

    for (int k0 = 0; k0 < DH; k0 += 8) {
        float4 av = *(const float4*)(Ap + k0);
        float4 bv = *(const float4*)(Bp + k0);
        As[lc4+0][lrow] = av.x; As[lc4+1][lrow] = av.y;
        As[lc4+2][lrow] = av.z; As[lc4+3][lrow] = av.w;
        Bs[lc4+0][lrow] = bv.x; Bs[lc4+1][lrow] = bv.y;
        Bs[lc4+2][lrow] = bv.z; Bs[lc4+3][lrow] = bv.w;
        __syncthreads();
#pragma unroll
        for (int kk = 0; kk < 8; kk++) {
            float4 a0 = *(const float4*)&As[kk][ty*8];
            float4 a1 = *(const float4*)&As[kk][ty*8+4];
            float4 b0 = *(const float4*)&Bs[kk][tx*8];
            float4 b1 = *(const float4*)&Bs[kk][tx*8+4];
            float a[8] = {a0.x,a0.y,a0.z,a0.w,a1.x,a1.y,a1.z,a1.w};
            float b[8] = {b0.x,b0.y,b0.z,b0.w,b1.x,b1.y,b1.z,b1.w};
#pragma unroll
            for (int i = 0; i < 8; i++)
#pragma unroll
                for (int j = 0; j < 8; j++)
                    acc[i][j] = fmaf(a[i], b[j], acc[i][j]);
        }
        __syncthreads();
    }

    const float scale = 0.08838834764831845f;  // 1/sqrt(128)
#pragma unroll
    for (int i = 0; i < 8; i++)
#pragma unroll
        for (int j = 0; j < 8; j++) acc[i][j] *= scale;

    if (h < NHG) {
        const float gs  = gscale[h];
        const int   np  = (h < NSYM) ? 2 : 1;
        const float wgs = gs * ((h < NSYM) ? 0.5f : 1.f);
        for (int p = 0; p < np; p++) {
            const int rqr = p ? j0 : i0;  // Rq rows loaded
            const int rkr = p ? i0 : j0;  // Rk rows loaded
#pragma unroll
            for (int it = 0; it < 4; it++) {
                int lin = tid + it * 256;
                int row = lin >> 3;
                int c4  = (lin & 7) << 2;
                float4 a = *(const float4*)(g_rq + (size_t)(rqr + row) * RLD + h * RDIM + c4);
                float4 b = *(const float4*)(g_rk + (size_t)(rkr + row) * RLD + h * RDIM + c4);
                Rq_s[row][c4+0]=a.x; Rq_s[row][c4+1]=a.y; Rq_s[row][c4+2]=a.z; Rq_s[row][c4+3]=a.w;
                Rk_s[row][c4+0]=b.x; Rk_s[row][c4+1]=b.y; Rk_s[row][c4+2]=b.z; Rk_s[row][c4+3]=b.w;
            }
            __syncthreads();
#pragma unroll 8
            for (int r = 0; r < RDIM; r++) {
                float a[8], b[8];
                if (p == 0) {
#pragma unroll
                    for (int i = 0; i < 8; i++) a[i] = Rq_s[ty*8+i][r] * wgs;
#pragma unroll
                    for (int j = 0; j < 8; j++) b[j] = Rk_s[tx*8+j][r];
                } else {
#pragma unroll
                    for (int i = 0; i < 8; i++) a[i] = Rk_s[ty*8+i][r] * wgs;
#pragma unroll
                    for (int j = 0; j < 8; j++) b[j] = Rq_s[tx*8+j][r];
                }
#pragma unroll
                for (int i = 0; i < 8; i++)
#pragma unroll
                    for (int j = 0; j < 8; j++)
                        acc[i][j] = fmaf(a[i], b[j], acc[i][j]);
            }
            __syncthreads();
        }
    }

#pragma unroll
    for (int i = 0; i < 8; i++) {
        const int gi = i0 + ty*8 + i;
        float* Cp = g_sc + ((size_t)h * SDIM + gi) * SDIM + j0 + tx*8;
#pragma unroll
        for (int j = 0; j < 8; j++) {
            const int gj = j0 + tx*8 + j;
            Cp[j] = (gj <= gi) ? acc[i][j] : 0.f;  // masked -> 0, never read by softmax
        }
    }
}

// ---------------------------------------------------------------------------
// Row softmax over valid length (i+1); in-place in g_sc. Row cached in smem.
// ---------------------------------------------------------------------------
__global__ __launch_bounds__(256) void softmax_kernel()
{
    const int i = blockIdx.x, h = blockIdx.y;
    const int len = i + 1;
    float* row = g_sc + ((size_t)h * SDIM + i) * SDIM;
    __shared__ float buf[SDIM];
    __shared__ float red[8];
    const int tid = threadIdx.x;

    float m = -3.4e38f;
    for (int j = tid; j < len; j += 256) { float v = row[j]; buf[j] = v; m = fmaxf(m, v); }
#pragma unroll
    for (int o = 16; o; o >>= 1) m = fmaxf(m, __shfl_xor_sync(0xffffffffu, m, o));
    if ((tid & 31) == 0) red[tid >> 5] = m;
    __syncthreads();
    m = red[0];
#pragma unroll
    for (int q = 1; q < 8; q++) m = fmaxf(m, red[q]);
    __syncthreads();

    float sum = 0.f;
    for (int j = tid; j < len; j += 256) { float e = __expf(buf[j] - m); buf[j] = e; sum += e; }
#pragma unroll
    for (int o = 16; o; o >>= 1) sum += __shfl_xor_sync(0xffffffffu, sum, o);
    if ((tid & 31) == 0) red[tid >> 5] = sum;
    __syncthreads();
    sum = red[0] + red[1] + red[2] + red[3] + red[4] + red[5] + red[6] + red[7];
    const float inv = 1.f / sum;
    for (int j = tid; j < len; j += 256) row[j] = buf[j] * inv;
}

// ---------------------------------------------------------------------------
// AV: out[i, h*128+d] = sum_j attn[h,i,j] * v[j, (h/4)*128+d]; causal K-trunc.
// ---------------------------------------------------------------------------
__global__ __launch_bounds__(256) void gemm_av()
{
    __shared__ float As[8][128];
    __shared__ float Bs[8][128];
    const int h = blockIdx.y;
    const int m0 = blockIdx.x << 7;
    const int kvh = h >> 2;
    const int tid = threadIdx.x;
    const int ty = tid >> 4, tx = tid & 15;
    const int lrow = tid >> 1, lc4 = (tid & 1) << 2;
    const int brow = tid >> 5, bc4 = (tid & 31) << 2;

    const float* Ap = g_sc + ((size_t)h * SDIM + m0 + lrow) * SDIM + lc4;
    const float* Bp = g_v + kvh * DH + bc4;

    float acc[8][8];
#pragma unroll
    for (int i = 0; i < 8; i++)
#pragma unroll
        for (int j = 0; j < 8; j++) acc[i][j] = 0.f;

    const int kmax = m0 + 128;  // attn is 0 above the diagonal within the tile band
    for (int k0 = 0; k0 < kmax; k0 += 8) {
        float4 av = *(const float4*)(Ap + k0);
        float4 bv = *(const float4*)(Bp + (size_t)(k0 + brow) * KVLD);
        As[lc4+0][lrow] = av.x; As[lc4+1][lrow] = av.y;
        As[lc4+2][lrow] = av.z; As[lc4+3][lrow] = av.w;
        *(float4*)&Bs[brow][bc4] = bv;
        __syncthreads();
#pragma unroll
        for (int kk = 0; kk < 8; kk++) {
            float4 a0 = *(const float4*)&As[kk][ty*8];
            float4 a1 = *(const float4*)&As[kk][ty*8+4];
            float4 b0 = *(const float4*)&Bs[kk][tx*8];
            float4 b1 = *(const float4*)&Bs[kk][tx*8+4];
            float a[8] = {a0.x,a0.y,a0.z,a0.w,a1.x,a1.y,a1.z,a1.w};
            float b[8] = {b0.x,b0.y,b0.z,b0.w,b1.x,b1.y,b1.z,b1.w};
#pragma unroll
            for (int i = 0; i < 8; i++)
#pragma unroll
                for (int j = 0; j < 8; j++)
                    acc[i][j] = fmaf(a[i], b[j], acc[i][j]);
        }
        __syncthreads();
    }
#pragma unroll
    for (int i = 0; i < 8; i++) {
        float* Cp = g_ao + (size_t)(m0 + ty*8 + i) * EDIM + h * DH + tx*8;
        *(float4*)(Cp)   = make_float4(acc[i][0],acc[i][1],acc[i][2],acc[i][3]);
        *(float4*)(Cp+4) = make_float4(acc[i][4],acc[i][5],acc[i][6],acc[i][7]);
    }
}

// ---------------------------------------------------------------------------
extern "C" void kernel_launch(void* const* d_in, const int* in_sizes, int n_in,
                              void* d_out, int out_size)
{
    const float* x   = (const float*)d_in[0];
    const float* Wq  = (const float*)d_in[1];
    const float* Wk  = (const float*)d_in[2];
    const float* Wv  = (const float*)d_in[3];
    const float* Wo  = (const float*)d_in[4];
    const float* qnw = (const float*)d_in[5];
    const float* knw = (const float*)d_in[6];
    const float* Wrq = (const float*)d_in[7];
    const float* Wrk = (const float*)d_in[8];
    const float* gsc = (const float*)d_in[9];
    float* out = (float*)d_out;

    float *q, *k, *v, *rq, *rk, *ao;
    cudaGetSymbolAddress((void**)&q,  g_q);
    cudaGetSymbolAddress((void**)&k,  g_k);
    cudaGetSymbolAddress((void**)&v,  g_v);
    cudaGetSymbolAddress((void**)&rq, g_rq);
    cudaGetSymbolAddress((void**)&rk, g_rk);
    cudaGetSymbolAddress((void**)&ao, g_ao);

    // Projections
    gemm_nt<<<dim3(16,16), 256>>>(x, EDIM, Wq,  EDIM, q,  EDIM, EDIM);
    gemm_nt<<<dim3(4, 16), 256>>>(x, EDIM, Wk,  EDIM, k,  KVLD, EDIM);
    gemm_nt<<<dim3(4, 16), 256>>>(x, EDIM, Wv,  EDIM, v,  KVLD, EDIM);
    gemm_nt<<<dim3(3, 16), 256>>>(x, EDIM, Wrq, EDIM, rq, RLD,  EDIM);
    gemm_nt<<<dim3(3, 16), 256>>>(x, EDIM, Wrk, EDIM, rk, RLD,  EDIM);

    // RMSNorm + RoPE
    norm_rope<<<dim3(SDIM, NH),  128>>>(q, qnw, EDIM);
    norm_rope<<<dim3(SDIM, NKV), 128>>>(k, knw, KVLD);

    // Scores (+bias, causal), softmax, AV
    scores_kernel<<<dim3(136, NH), 256>>>(gsc);
    softmax_kernel<<<dim3(SDIM, NH), 256>>>();
    gemm_av<<<dim3(16, NH), 256>>>();

    // Output projection
    gemm_nt<<<dim3(16,16), 256>>>(ao, EDIM, Wo, EDIM, out, EDIM, EDIM);
}